// round 1
// baseline (speedup 1.0000x reference)
#include <cuda_runtime.h>

// Sparse CG tensor product:
//   out[b, M[i]] += scale[i] * x[b, M1[i]] * y[b, M2[i]]
// B = 20000, DIM = 512, NNZ = 5000 (but read sizes from in_sizes).
//
// Strategy: lane = batch row (32 rows per CTA). All 32 lanes of a warp process
// the SAME path i => gather smem address = m1*PAD + lane = const + lane, which
// is bank-conflict-free by construction. M is sorted => register accumulation
// per output column with a single store on column change; path ranges are
// split across warps at segment boundaries so there are NO atomics anywhere.

#define DIMC   512
#define PAD    33
#define TILE   (DIMC * PAD)          // 16896 floats per tile
#define NWARP  8
#define NTHR   (NWARP * 32)          // 256
#define CHUNK  128                   // paths staged per warp per chunk
#define MAXNNZ 8192

// persistent device scratch (no allocations allowed)
__device__ int4 g_paths[MAXNNZ];     // {M*PAD, M1*PAD, M2*PAD, bits(scale)}
__device__ int  g_wstart[NWARP + 1]; // per-warp path ranges (segment-aligned)

// ---------------------------------------------------------------------------
// Setup: pack path table + compute segment-aligned warp split points.
// ---------------------------------------------------------------------------
__global__ void pack_kernel(const float* __restrict__ scale,
                            const int* __restrict__ M,
                            const int* __restrict__ M1,
                            const int* __restrict__ M2,
                            int nnz)
{
    int i = blockIdx.x * blockDim.x + threadIdx.x;
    if (i < nnz) {
        g_paths[i] = make_int4(M[i] * PAD, M1[i] * PAD, M2[i] * PAD,
                               __float_as_int(scale[i]));
    }
    if (i == 0) {
        g_wstart[0] = 0;
        g_wstart[NWARP] = nnz;
        int prev = 0;
        for (int w = 1; w < NWARP; w++) {
            int t = (int)(((long long)w * nnz) / NWARP);
            if (t < prev) t = prev;
            // advance to a segment boundary (M sorted) so each output column
            // has exactly one owning warp
            while (t > 0 && t < nnz && M[t] == M[t - 1]) t++;
            g_wstart[w] = t;
            prev = t;
        }
    }
}

// ---------------------------------------------------------------------------
// Main kernel: one CTA = 32 batch rows, 8 warps split the path list.
// ---------------------------------------------------------------------------
__global__ __launch_bounds__(NTHR, 1)
void tp_kernel(const float* __restrict__ x,
               const float* __restrict__ y,
               float* __restrict__ out,
               int Brows)
{
    extern __shared__ float sm[];
    float* xs = sm;                   // [DIMC][PAD], col = batch row
    float* ys = sm + TILE;
    float* os = sm + 2 * TILE;
    int4*  spath = (int4*)(sm + 3 * TILE);   // [NWARP][CHUNK]

    const int tid  = threadIdx.x;
    const int lane = tid & 31;
    const int warp = tid >> 5;
    const int b0   = blockIdx.x << 5;
    const int nb   = min(32, Brows - b0);

    // ---- load x/y tiles (coalesced float4 in GMEM, transposed into smem) ----
    if (nb == 32) {
        const float4* x4 = (const float4*)(x + (size_t)b0 * DIMC);
        const float4* y4 = (const float4*)(y + (size_t)b0 * DIMC);
        #pragma unroll 4
        for (int idx = tid; idx < 32 * (DIMC / 4); idx += NTHR) {
            int b  = idx >> 7;        // 0..31
            int d4 = idx & 127;       // 0..127
            float4 vx = x4[b * (DIMC / 4) + d4];
            float4 vy = y4[b * (DIMC / 4) + d4];
            int d = d4 << 2;
            xs[(d + 0) * PAD + b] = vx.x;
            xs[(d + 1) * PAD + b] = vx.y;
            xs[(d + 2) * PAD + b] = vx.z;
            xs[(d + 3) * PAD + b] = vx.w;
            ys[(d + 0) * PAD + b] = vy.x;
            ys[(d + 1) * PAD + b] = vy.y;
            ys[(d + 2) * PAD + b] = vy.z;
            ys[(d + 3) * PAD + b] = vy.w;
        }
    } else {
        for (int idx = tid; idx < 32 * DIMC; idx += NTHR) {
            int b = idx >> 9;
            int d = idx & 511;
            float vx = 0.f, vy = 0.f;
            if (b < nb) {
                vx = x[(size_t)(b0 + b) * DIMC + d];
                vy = y[(size_t)(b0 + b) * DIMC + d];
            }
            xs[d * PAD + b] = vx;
            ys[d * PAD + b] = vy;
        }
    }
    // ---- zero output tile ----
    for (int idx = tid; idx < TILE; idx += NTHR) os[idx] = 0.f;
    __syncthreads();

    // ---- per-warp path processing ----
    const int istart = g_wstart[warp];
    const int iend   = g_wstart[warp + 1];

    if (istart < iend) {
        int4* sp = spath + warp * CHUNK;
        const float* xsl = xs + lane;
        const float* ysl = ys + lane;
        float*       osl = os + lane;

        // prefetch chunk 0 into registers (coalesced LDG.128)
        int4 r0, r1, r2, r3;
        {
            int i0 = istart + lane;
            r0 = (i0       < iend) ? g_paths[i0]       : make_int4(0, 0, 0, 0);
            r1 = (i0 + 32  < iend) ? g_paths[i0 + 32]  : make_int4(0, 0, 0, 0);
            r2 = (i0 + 64  < iend) ? g_paths[i0 + 64]  : make_int4(0, 0, 0, 0);
            r3 = (i0 + 96  < iend) ? g_paths[i0 + 96]  : make_int4(0, 0, 0, 0);
        }

        float acc  = 0.f;
        int   mcur = __shfl_sync(0xffffffffu, r0.x, 0);  // first path's M*PAD

        for (int base = istart; base < iend; base += CHUNK) {
            // publish current chunk to shared
            sp[lane]      = r0;
            sp[lane + 32] = r1;
            sp[lane + 64] = r2;
            sp[lane + 96] = r3;
            __syncwarp();

            // prefetch next chunk (overlaps with processing below)
            {
                int i0 = base + CHUNK + lane;
                r0 = (i0      < iend) ? g_paths[i0]      : make_int4(0, 0, 0, 0);
                r1 = (i0 + 32 < iend) ? g_paths[i0 + 32] : make_int4(0, 0, 0, 0);
                r2 = (i0 + 64 < iend) ? g_paths[i0 + 64] : make_int4(0, 0, 0, 0);
                r3 = (i0 + 96 < iend) ? g_paths[i0 + 96] : make_int4(0, 0, 0, 0);
            }

            const int cnt = min(CHUNK, iend - base);
            #pragma unroll 4
            for (int j = 0; j < cnt; j++) {
                int4 p = sp[j];                        // broadcast LDS.128 (free)
                if (p.x != mcur) {                     // warp-uniform branch
                    osl[mcur] = acc;                   // single owner, no atomic
                    acc  = 0.f;
                    mcur = p.x;
                }
                // conflict-free gathers: address = uniform + lane
                acc = fmaf(__int_as_float(p.w) * xsl[p.y], ysl[p.z], acc);
            }
            __syncwarp();
        }
        osl[mcur] = acc;   // final flush
    }
    __syncthreads();

    // ---- write back output tile (coalesced float4) ----
    if (nb == 32) {
        float4* o4 = (float4*)(out + (size_t)b0 * DIMC);
        #pragma unroll 4
        for (int idx = tid; idx < 32 * (DIMC / 4); idx += NTHR) {
            int b  = idx >> 7;
            int d4 = idx & 127;
            int d  = d4 << 2;
            float4 v;
            v.x = os[(d + 0) * PAD + b];
            v.y = os[(d + 1) * PAD + b];
            v.z = os[(d + 2) * PAD + b];
            v.w = os[(d + 3) * PAD + b];
            o4[b * (DIMC / 4) + d4] = v;
        }
    } else {
        for (int idx = tid; idx < 32 * DIMC; idx += NTHR) {
            int b = idx >> 9;
            int d = idx & 511;
            if (b < nb) out[(size_t)(b0 + b) * DIMC + d] = os[d * PAD + b];
        }
    }
}

// ---------------------------------------------------------------------------
// Launch
// ---------------------------------------------------------------------------
extern "C" void kernel_launch(void* const* d_in, const int* in_sizes, int n_in,
                              void* d_out, int out_size)
{
    const float* x     = (const float*)d_in[0];
    const float* y     = (const float*)d_in[1];
    const float* scale = (const float*)d_in[2];
    const int*   M     = (const int*)d_in[3];
    const int*   M1    = (const int*)d_in[4];
    const int*   M2    = (const int*)d_in[5];
    float*       out   = (float*)d_out;

    const int B   = in_sizes[0] / DIMC;
    const int nnz = in_sizes[2];

    // opt into large dynamic smem (idempotent; persists across graph replays)
    static const size_t smem_bytes = (size_t)3 * TILE * sizeof(float)
                                   + (size_t)NWARP * CHUNK * sizeof(int4); // 219136
    cudaFuncSetAttribute(tp_kernel, cudaFuncAttributeMaxDynamicSharedMemorySize,
                         (int)smem_bytes);

    pack_kernel<<<(nnz + 255) / 256, 256>>>(scale, M, M1, M2, nnz);

    const int nblocks = (B + 31) / 32;
    tp_kernel<<<nblocks, NTHR, smem_bytes>>>(x, y, out, B);
}

// round 4
// speedup vs baseline: 1.2420x; 1.2420x over previous
#include <cuda_runtime.h>

// Sparse CG tensor product:
//   out[b, M[i]] += scale[i] * x[b, M1[i]] * y[b, M2[i]]
//
// One CTA = 32 batch rows. Tiles in smem as [32 rows][stride 513].
// Gather addr = lane*513 + m  =>  bank (lane*513 + m) % 32 = (lane + m) % 32,
// a permutation over lanes => conflict-free by construction.
// Rows are NOT 16B aligned (513 odd), so all smem tile fill/drain is scalar,
// mapped lane -> consecutive d (consecutive addrs => conflict-free; GMEM
// fully coalesced).
// All 32 lanes of a warp process the SAME path => path metadata is one
// broadcast LDS.128. M sorted => register accumulation with one smem store
// per column change; per-warp path ranges are segment-aligned => single
// writer per output column, no atomics anywhere.

#define DIMC    512
#define STRIDE  513
#define TILE    (32 * STRIDE)          // 16416 floats
#define NWARP   16
#define NTHR    (NWARP * 32)           // 512
#define CHUNK   64
#define MAXNNZ  8192

__device__ int4 g_paths[MAXNNZ];       // {M, M1, M2, bits(scale)}  (RAW indices)
__device__ int  g_wstart[NWARP + 1];

// ---------------------------------------------------------------------------
__global__ void pack_kernel(const float* __restrict__ scale,
                            const int* __restrict__ M,
                            const int* __restrict__ M1,
                            const int* __restrict__ M2,
                            int nnz)
{
    int i = blockIdx.x * blockDim.x + threadIdx.x;
    if (i < nnz) {
        // RAW indices: the lane supplies the row-stride term in the main kernel.
        g_paths[i] = make_int4(M[i], M1[i], M2[i], __float_as_int(scale[i]));
    }
    if (i == 0) {
        g_wstart[0] = 0;
        g_wstart[NWARP] = nnz;
        int prev = 0;
        for (int w = 1; w < NWARP; w++) {
            int t = (int)(((long long)w * nnz) / NWARP);
            if (t < prev) t = prev;
            while (t > 0 && t < nnz && M[t] == M[t - 1]) t++;  // segment align
            g_wstart[w] = t;
            prev = t;
        }
    }
}

// ---------------------------------------------------------------------------
__global__ __launch_bounds__(NTHR, 1)
void tp_kernel(const float* __restrict__ x,
               const float* __restrict__ y,
               float* __restrict__ out,
               int Brows)
{
    extern __shared__ float sm[];
    float* xs = sm;                          // [32][STRIDE]
    float* ys = sm + TILE;
    float* os = sm + 2 * TILE;
    int4*  spath = (int4*)(sm + 3 * TILE);   // [NWARP][CHUNK]

    const int tid  = threadIdx.x;
    const int lane = tid & 31;
    const int warp = tid >> 5;
    const int b0   = blockIdx.x << 5;
    const int nb   = min(32, Brows - b0);

    // ---- fill tiles + zero output tile (scalar, conflict-free, coalesced) ----
    if (nb == 32) {
        #pragma unroll
        for (int it = 0; it < (32 * DIMC) / NTHR; it++) {
            int idx = it * NTHR + tid;
            int b = idx >> 9;
            int d = idx & 511;
            size_t g = (size_t)(b0 + b) * DIMC + d;
            int s = b * STRIDE + d;
            xs[s] = x[g];
            ys[s] = y[g];
            os[s] = 0.f;
        }
    } else {
        for (int idx = tid; idx < 32 * DIMC; idx += NTHR) {
            int b = idx >> 9;
            int d = idx & 511;
            float vx = 0.f, vy = 0.f;
            if (b < nb) {
                size_t g = (size_t)(b0 + b) * DIMC + d;
                vx = x[g];
                vy = y[g];
            }
            int s = b * STRIDE + d;
            xs[s] = vx;
            ys[s] = vy;
            os[s] = 0.f;
        }
    }
    __syncthreads();

    // ---- per-warp path processing ----
    const int istart = g_wstart[warp];
    const int iend   = g_wstart[warp + 1];

    if (istart < iend) {
        int4* sp = spath + warp * CHUNK;
        const float* xsl = xs + lane * STRIDE;
        const float* ysl = ys + lane * STRIDE;
        float*       osl = os + lane * STRIDE;

        // prefetch chunk 0 (coalesced LDG.128)
        int4 r0, r1;
        {
            int i0 = istart + lane;
            r0 = (i0      < iend) ? g_paths[i0]      : make_int4(0, 0, 0, 0);
            r1 = (i0 + 32 < iend) ? g_paths[i0 + 32] : make_int4(0, 0, 0, 0);
        }

        float acc  = 0.f;
        int   mcur = __shfl_sync(0xffffffffu, r0.x, 0);

        for (int base = istart; base < iend; base += CHUNK) {
            sp[lane]      = r0;
            sp[lane + 32] = r1;
            __syncwarp();

            // prefetch next chunk (overlaps processing)
            {
                int i0 = base + CHUNK + lane;
                r0 = (i0      < iend) ? g_paths[i0]      : make_int4(0, 0, 0, 0);
                r1 = (i0 + 32 < iend) ? g_paths[i0 + 32] : make_int4(0, 0, 0, 0);
            }

            const int cnt = min(CHUNK, iend - base);
            #pragma unroll 4
            for (int j = 0; j < cnt; j++) {
                int4 p = sp[j];                 // broadcast LDS.128
                if (p.x != mcur) {              // warp-uniform branch
                    osl[mcur] = acc;            // single owner, no atomic
                    acc  = 0.f;
                    mcur = p.x;
                }
                acc = fmaf(__int_as_float(p.w) * xsl[p.y], ysl[p.z], acc);
            }
            __syncwarp();
        }
        osl[mcur] = acc;                        // final flush
    }
    __syncthreads();

    // ---- drain output tile (scalar LDS, coalesced STG) ----
    if (nb == 32) {
        #pragma unroll
        for (int it = 0; it < (32 * DIMC) / NTHR; it++) {
            int idx = it * NTHR + tid;
            int b = idx >> 9;
            int d = idx & 511;
            out[(size_t)(b0 + b) * DIMC + d] = os[b * STRIDE + d];
        }
    } else {
        for (int idx = tid; idx < 32 * DIMC; idx += NTHR) {
            int b = idx >> 9;
            int d = idx & 511;
            if (b < nb) out[(size_t)(b0 + b) * DIMC + d] = os[b * STRIDE + d];
        }
    }
}

// ---------------------------------------------------------------------------
extern "C" void kernel_launch(void* const* d_in, const int* in_sizes, int n_in,
                              void* d_out, int out_size)
{
    const float* x     = (const float*)d_in[0];
    const float* y     = (const float*)d_in[1];
    const float* scale = (const float*)d_in[2];
    const int*   M     = (const int*)d_in[3];
    const int*   M1    = (const int*)d_in[4];
    const int*   M2    = (const int*)d_in[5];
    float*       out   = (float*)d_out;

    const int B   = in_sizes[0] / DIMC;
    const int nnz = in_sizes[2];

    const size_t smem_bytes = (size_t)3 * TILE * sizeof(float)
                            + (size_t)NWARP * CHUNK * sizeof(int4); // 213376 B
    cudaFuncSetAttribute(tp_kernel, cudaFuncAttributeMaxDynamicSharedMemorySize,
                         (int)smem_bytes);

    pack_kernel<<<(nnz + 255) / 256, 256>>>(scale, M, M1, M2, nnz);

    const int nblocks = (B + 31) / 32;
    tp_kernel<<<nblocks, NTHR, smem_bytes>>>(x, y, out, B);
}